// round 4
// baseline (speedup 1.0000x reference)
#include <cuda_runtime.h>

// result = 2*(C-1)/C^2 * mean(|ct|)  with C=8, H=W=512
// Derivation: per pixel, sum over (c,l) of |v*[l==t] - v*[c==q]| = 2*(C-1)*|v|,
// independent of t (target label) and q (argmax of pred). pred_stage1 and
// target never need to be read.

#define NUM_BLOCKS 256
#define NUM_THREADS 256

__device__ float g_partials[NUM_BLOCKS];

__global__ void __launch_bounds__(NUM_THREADS)
abs_sum_stage1(const float4* __restrict__ ct4, int n4) {
    int idx = blockIdx.x * NUM_THREADS + threadIdx.x;
    float s = 0.0f;
    // grid-stride for generality; for 512x512 each thread does exactly 1 iter
    for (int i = idx; i < n4; i += NUM_BLOCKS * NUM_THREADS) {
        float4 v = ct4[i];
        s += fabsf(v.x) + fabsf(v.y) + fabsf(v.z) + fabsf(v.w);
    }
    // warp reduce
    #pragma unroll
    for (int o = 16; o > 0; o >>= 1)
        s += __shfl_xor_sync(0xffffffffu, s, o);
    __shared__ float ws[NUM_THREADS / 32];
    if ((threadIdx.x & 31) == 0) ws[threadIdx.x >> 5] = s;
    __syncthreads();
    if (threadIdx.x < NUM_THREADS / 32) {
        float t = ws[threadIdx.x];
        #pragma unroll
        for (int o = (NUM_THREADS / 32) / 2; o > 0; o >>= 1)
            t += __shfl_xor_sync(0xffu, t, o);
        if (threadIdx.x == 0) g_partials[blockIdx.x] = t;
    }
}

__global__ void __launch_bounds__(NUM_BLOCKS)
abs_sum_stage2(float* __restrict__ out, float scale) {
    float s = g_partials[threadIdx.x];
    #pragma unroll
    for (int o = 16; o > 0; o >>= 1)
        s += __shfl_xor_sync(0xffffffffu, s, o);
    __shared__ float ws[NUM_BLOCKS / 32];
    if ((threadIdx.x & 31) == 0) ws[threadIdx.x >> 5] = s;
    __syncthreads();
    if (threadIdx.x == 0) {
        float t = 0.0f;
        #pragma unroll
        for (int i = 0; i < NUM_BLOCKS / 32; i++) t += ws[i];
        out[0] = t * scale;
    }
}

extern "C" void kernel_launch(void* const* d_in, const int* in_sizes, int n_in,
                              void* d_out, int out_size) {
    // inputs: [0] pred_stage1 f32 (unused), [1] ct f32, [2] target i64 (unused)
    const float* ct = (const float*)d_in[1];
    int n = in_sizes[1];          // H*W = 262144
    int n4 = n / 4;

    const int C = 8;
    float scale = (2.0f * (C - 1)) / ((float)(C * C)) / (float)n;

    abs_sum_stage1<<<NUM_BLOCKS, NUM_THREADS>>>((const float4*)ct, n4);
    abs_sum_stage2<<<1, NUM_BLOCKS>>>((float*)d_out, scale);
}